// round 2
// baseline (speedup 1.0000x reference)
#include <cuda_runtime.h>

typedef unsigned long long ull;

#define TLEN 512
#define BSZ  128
#define MDIM 31
#define HSZ  512
#define ESZ  256
#define SSZ  128
#define G3   1536
#define TB   65536      // TLEN*BSZ
#define NSTEP 511
#define NGRU_BLK 128
#define NPAIR 65408     // 511*128
#define NB4B  8176      // NPAIR/8
#define LOG2PI 1.8378770664093453f

// ---------------- scratch (device globals; no allocation) ----------------
__device__ float g_phi[TB * ESZ];                    //  64 MB
__device__ float g_xg[(size_t)TB * G3];              // 402 MB
__device__ float g_hs[(size_t)TLEN * BSZ * HSZ];     // 134 MB
__device__ float g_he[(size_t)TB * SSZ];             //  33 MB
__device__ float g_partial[NB4B];
__device__ unsigned g_arrive;

// ---------------- f32x2 packed-FMA helpers ----------------
__device__ __forceinline__ ull pk2(float x, float y) {
    ull r; asm("mov.b64 %0, {%1, %2};" : "=l"(r) : "f"(x), "f"(y)); return r;
}
__device__ __forceinline__ ull fma2(ull a, ull b, ull c) {
    ull d; asm("fma.rn.f32x2 %0, %1, %2, %3;" : "=l"(d) : "l"(a), "l"(b), "l"(c)); return d;
}
__device__ __forceinline__ float2 up2(ull v) {
    float2 f; asm("mov.b64 {%0, %1}, %2;" : "=f"(f.x), "=f"(f.y) : "l"(v)); return f;
}
__device__ __forceinline__ float sigm(float v) { return 1.f / (1.f + __expf(-v)); }

// ---------------- K0: init (zero h0, reset barrier) ----------------
__global__ void k0_init() {
    int idx = blockIdx.x * 256 + threadIdx.x;
    if (idx < BSZ * HSZ) g_hs[idx] = 0.f;
    if (idx == 0) g_arrive = 0u;
}

// ---------------- K1: phi = relu(x @ W_embed^T + b_embed) ----------------
__global__ void __launch_bounds__(256) k1_embed(const float* __restrict__ x,
                                                const float* __restrict__ W_embed,
                                                const float* __restrict__ b_embed) {
    __shared__ float sx[64][32];
    const int tid = threadIdx.x;
    const int row0 = blockIdx.x * 64;
    for (int idx = tid; idx < 64 * MDIM; idx += 256) {
        int r = idx / MDIM, c = idx - r * MDIM;
        sx[r][c] = x[(size_t)(row0 + r) * MDIM + c];
    }
    float wreg[MDIM];
    const float* wp = W_embed + tid * MDIM;   // tid in [0,256) == ESZ
#pragma unroll
    for (int k = 0; k < MDIM; k++) wreg[k] = __ldg(wp + k);
    float bb = __ldg(b_embed + tid);
    __syncthreads();
#pragma unroll 4
    for (int r = 0; r < 64; r++) {
        float acc = bb;
#pragma unroll
        for (int k = 0; k < MDIM; k++) acc += sx[r][k] * wreg[k];
        g_phi[(size_t)(row0 + r) * ESZ + tid] = fmaxf(acc, 0.f);
    }
}

// ---------------- shared GEMM body: C[m,n] = act(sum_k A[m,k]*B[n,k] + bias[n]) ----------------
// BM=BN=128, BK=16, 256 threads, 8x8 microtile, f32x2 accumulation.
__device__ __forceinline__ void gemm_body(const float* __restrict__ A, const float* __restrict__ B,
                                          const float* __restrict__ bias, float* __restrict__ C,
                                          int KD, int N, bool relu) {
    __shared__ float As[16][128];
    __shared__ float Bs[16][128];
    const int tid = threadIdx.x;
    const int m0 = blockIdx.x * 128, n0 = blockIdx.y * 128;
    const int lr = tid >> 1, ls = (tid & 1) * 8;
    const int tx = tid & 15, ty = tid >> 4;
    ull acc[8][4];
#pragma unroll
    for (int i = 0; i < 8; i++)
#pragma unroll
        for (int j = 0; j < 4; j++) acc[i][j] = 0ull;

    const float* Ap = A + (size_t)(m0 + lr) * KD + ls;
    const float* Bp = B + (size_t)(n0 + lr) * KD + ls;

    for (int kt = 0; kt < KD; kt += 16) {
        float4 a0 = *(const float4*)(Ap + kt);
        float4 a1 = *(const float4*)(Ap + kt + 4);
        float4 b0 = *(const float4*)(Bp + kt);
        float4 b1 = *(const float4*)(Bp + kt + 4);
        __syncthreads();
        As[ls + 0][lr] = a0.x; As[ls + 1][lr] = a0.y; As[ls + 2][lr] = a0.z; As[ls + 3][lr] = a0.w;
        As[ls + 4][lr] = a1.x; As[ls + 5][lr] = a1.y; As[ls + 6][lr] = a1.z; As[ls + 7][lr] = a1.w;
        Bs[ls + 0][lr] = b0.x; Bs[ls + 1][lr] = b0.y; Bs[ls + 2][lr] = b0.z; Bs[ls + 3][lr] = b0.w;
        Bs[ls + 4][lr] = b1.x; Bs[ls + 5][lr] = b1.y; Bs[ls + 6][lr] = b1.z; Bs[ls + 7][lr] = b1.w;
        __syncthreads();
#pragma unroll
        for (int k = 0; k < 16; k++) {
            float4 av0 = *(const float4*)&As[k][ty * 8];
            float4 av1 = *(const float4*)&As[k][ty * 8 + 4];
            float4 bv0 = *(const float4*)&Bs[k][tx * 8];
            float4 bv1 = *(const float4*)&Bs[k][tx * 8 + 4];
            ull bp0 = pk2(bv0.x, bv0.y), bp1 = pk2(bv0.z, bv0.w);
            ull bp2 = pk2(bv1.x, bv1.y), bp3 = pk2(bv1.z, bv1.w);
            float aa[8] = {av0.x, av0.y, av0.z, av0.w, av1.x, av1.y, av1.z, av1.w};
#pragma unroll
            for (int i = 0; i < 8; i++) {
                ull ap = pk2(aa[i], aa[i]);
                acc[i][0] = fma2(ap, bp0, acc[i][0]);
                acc[i][1] = fma2(ap, bp1, acc[i][1]);
                acc[i][2] = fma2(ap, bp2, acc[i][2]);
                acc[i][3] = fma2(ap, bp3, acc[i][3]);
            }
        }
    }
    float bvals[8];
#pragma unroll
    for (int j = 0; j < 8; j++) bvals[j] = __ldg(bias + n0 + tx * 8 + j);
#pragma unroll
    for (int i = 0; i < 8; i++) {
        int row = m0 + ty * 8 + i;
        float out[8]; float2 v;
        v = up2(acc[i][0]); out[0] = v.x; out[1] = v.y;
        v = up2(acc[i][1]); out[2] = v.x; out[3] = v.y;
        v = up2(acc[i][2]); out[4] = v.x; out[5] = v.y;
        v = up2(acc[i][3]); out[6] = v.x; out[7] = v.y;
#pragma unroll
        for (int j = 0; j < 8; j++) {
            float o = out[j] + bvals[j];
            if (relu) o = fmaxf(o, 0.f);
            out[j] = o;
        }
        float4* dst = (float4*)(C + (size_t)row * N + n0 + tx * 8);
        dst[0] = make_float4(out[0], out[1], out[2], out[3]);
        dst[1] = make_float4(out[4], out[5], out[6], out[7]);
    }
}

__global__ void __launch_bounds__(256) k2_gates(const float* __restrict__ W_ih,
                                                const float* __restrict__ b_ih) {
    gemm_body(g_phi, W_ih, b_ih, g_xg, ESZ, G3, false);
}
__global__ void __launch_bounds__(256) k4a_he(const float* __restrict__ W_he,
                                              const float* __restrict__ b_he) {
    gemm_body(g_hs, W_he, b_he, g_he, HSZ, SSZ, true);
}

// ---------------- K3: persistent GRU ----------------
// 128 blocks x 256 threads, one wave. Block owns 4 hidden units; thread = (batch i, unit-pair uu).
__global__ void __launch_bounds__(256) k3_gru(const float* __restrict__ W_hh,
                                              const float* __restrict__ b_hh) {
    __shared__ __align__(16) ull sW[3][2][512];   // packed (w_j0[k], w_j1[k]) pairs, 24 KB
    const int tid = threadIdx.x;
    const int base = blockIdx.x * 4;

    for (int idx = tid; idx < 3 * 2 * 512; idx += 256) {
        int k = idx & 511, uu_ = (idx >> 9) & 1, g = idx >> 10;
        int j0_ = base + uu_ * 2;
        float w0 = W_hh[(size_t)(g * HSZ + j0_) * HSZ + k];
        float w1 = W_hh[(size_t)(g * HSZ + j0_ + 1) * HSZ + k];
        sW[g][uu_][k] = pk2(w0, w1);
    }
    const int i  = tid & 127;
    const int uu = tid >> 7;
    const int j0 = base + uu * 2;
    const float bhr0 = __ldg(b_hh + j0),            bhr1 = __ldg(b_hh + j0 + 1);
    const float bhz0 = __ldg(b_hh + HSZ + j0),      bhz1 = __ldg(b_hh + HSZ + j0 + 1);
    const float bhn0 = __ldg(b_hh + 2 * HSZ + j0),  bhn1 = __ldg(b_hh + 2 * HSZ + j0 + 1);
    __syncthreads();

    const ulonglong2* wr = (const ulonglong2*)&sW[0][uu][0];
    const ulonglong2* wz = (const ulonglong2*)&sW[1][uu][0];
    const ulonglong2* wn = (const ulonglong2*)&sW[2][uu][0];

    for (int t = 0; t < NSTEP; t++) {
        const float* hcur = g_hs + (size_t)t * (BSZ * HSZ);
        float*       hnex = g_hs + (size_t)(t + 1) * (BSZ * HSZ);
        const float4* hrow = (const float4*)(hcur + i * HSZ);
        const float* xgr = g_xg + ((size_t)t * BSZ + i) * G3;

        // prefetch input-gate values + previous h for the 2 units we own
        float xr0 = __ldg(xgr + j0),           xr1 = __ldg(xgr + j0 + 1);
        float xz0 = __ldg(xgr + HSZ + j0),     xz1 = __ldg(xgr + HSZ + j0 + 1);
        float xn0 = __ldg(xgr + 2 * HSZ + j0), xn1 = __ldg(xgr + 2 * HSZ + j0 + 1);
        float hp0 = __ldg(hcur + i * HSZ + j0), hp1 = __ldg(hcur + i * HSZ + j0 + 1);

        ull accR = 0ull, accZ = 0ull, accN = 0ull;
#pragma unroll 8
        for (int kk = 0; kk < 128; kk++) {
            float4 hv = __ldg(&hrow[kk]);
            ull h0 = pk2(hv.x, hv.x), h1 = pk2(hv.y, hv.y);
            ull h2 = pk2(hv.z, hv.z), h3 = pk2(hv.w, hv.w);
            ulonglong2 wa, wb;
            wa = wr[2 * kk]; wb = wr[2 * kk + 1];
            accR = fma2(h0, wa.x, accR); accR = fma2(h1, wa.y, accR);
            accR = fma2(h2, wb.x, accR); accR = fma2(h3, wb.y, accR);
            wa = wz[2 * kk]; wb = wz[2 * kk + 1];
            accZ = fma2(h0, wa.x, accZ); accZ = fma2(h1, wa.y, accZ);
            accZ = fma2(h2, wb.x, accZ); accZ = fma2(h3, wb.y, accZ);
            wa = wn[2 * kk]; wb = wn[2 * kk + 1];
            accN = fma2(h0, wa.x, accN); accN = fma2(h1, wa.y, accN);
            accN = fma2(h2, wb.x, accN); accN = fma2(h3, wb.y, accN);
        }
        float2 hr = up2(accR), hz = up2(accZ), hn = up2(accN);
        {
            float r = sigm(xr0 + hr.x + bhr0);
            float z = sigm(xz0 + hz.x + bhz0);
            float n = tanhf(xn0 + r * (hn.x + bhn0));
            hnex[i * HSZ + j0] = (1.f - z) * n + z * hp0;
        }
        {
            float r = sigm(xr1 + hr.y + bhr1);
            float z = sigm(xz1 + hz.y + bhz1);
            float n = tanhf(xn1 + r * (hn.y + bhn1));
            hnex[i * HSZ + j0 + 1] = (1.f - z) * n + z * hp1;
        }
        // ---- grid barrier (monotonic counter) ----
        __threadfence();
        __syncthreads();
        if (tid == 0) {
            atomicAdd(&g_arrive, 1u);
            unsigned target = (unsigned)NGRU_BLK * (unsigned)(t + 1);
            while (*(volatile unsigned*)&g_arrive < target) { __nanosleep(64); }
            __threadfence();
        }
        __syncthreads();
    }
}

// ---------------- K4b: per-event loss (warp per (t,i)), partials per block ----------------
__global__ void __launch_bounds__(256) k4b_loss(const float* __restrict__ x,
                                                const float* __restrict__ tin,
                                                const float* __restrict__ maskp,
                                                const float* __restrict__ W_mu,
                                                const float* __restrict__ b_mu,
                                                const float* __restrict__ W_lv,
                                                const float* __restrict__ b_lv,
                                                const float* __restrict__ h_infl,
                                                const float* __restrict__ ti_p,
                                                const float* __restrict__ bi_p) {
    __shared__ float s_he[8][SSZ];
    __shared__ float s_red[8];
    const int tid = threadIdx.x;
    const int w = tid >> 5, lane = tid & 31;
    const int q = blockIdx.x * 8 + w;            // q in [0, 65408)
    const int t = (q >> 7) + 1;                  // t in [1, 512)
    const int i = q & 127;
    const size_t row = (size_t)t * BSZ + i;

    // stage he row into shared
    ((float4*)s_he[w])[lane] = ((const float4*)(g_he + row * SSZ))[lane];
    __syncwarp();

    // past = he . h_influence
    float p = 0.f;
#pragma unroll
    for (int kk = 0; kk < 4; kk++) {
        int k = lane + 32 * kk;
        p += s_he[w][k] * __ldg(h_infl + k);
    }
#pragma unroll
    for (int off = 16; off; off >>= 1) p += __shfl_xor_sync(0xffffffffu, p, off);

    // mu / logvar + marker LL for lane < 31
    float marker = 0.f;
    if (lane < MDIM) {
        float accm = __ldg(b_mu + lane);
        float accl = __ldg(b_lv + lane);
        const float4* wm = (const float4*)(W_mu + lane * SSZ);
        const float4* wl = (const float4*)(W_lv + lane * SSZ);
#pragma unroll 8
        for (int kk = 0; kk < 32; kk++) {
            float4 hev = ((const float4*)s_he[w])[kk];
            float4 a = __ldg(wm + kk);
            float4 b = __ldg(wl + kk);
            accm += hev.x * a.x + hev.y * a.y + hev.z * a.z + hev.w * a.w;
            accl += hev.x * b.x + hev.y * b.y + hev.z * b.z + hev.w * b.w;
        }
        float xv = __ldg(x + row * MDIM + lane);
        float sig = fmaxf(expf(0.5f * accl), 0.01f);
        float d = (xv - accm) / sig;
        marker = -0.5f * d * d - logf(sig) - 0.5f * LOG2PI;
    }
#pragma unroll
    for (int off = 16; off; off >>= 1) marker += __shfl_xor_sync(0xffffffffu, marker, off);

    if (lane == 0) {
        float ti = __ldg(ti_p);
        float bi = __ldg(bi_p);
        float dt = __ldg(tin + row * 2 + 1);
        float term1 = p + ti * dt + bi;
        float time_ll = term1 + (expf(p + bi) - expf(term1)) / ti;
        float m = __ldg(maskp + row);
        s_red[w] = (-time_ll - marker) * m;    // GAMMA = 1
    }
    __syncthreads();
    if (tid == 0) {
        float s = 0.f;
#pragma unroll
        for (int k = 0; k < 8; k++) s += s_red[k];
        g_partial[blockIdx.x] = s;
    }
}

// ---------------- K5: deterministic final reduce ----------------
__global__ void __launch_bounds__(256) k5_reduce(float* __restrict__ out) {
    __shared__ float s[256];
    const int tid = threadIdx.x;
    float a = 0.f;
    for (int idx = tid; idx < NB4B; idx += 256) a += g_partial[idx];
    s[tid] = a;
    __syncthreads();
    for (int off = 128; off; off >>= 1) {
        if (tid < off) s[tid] += s[tid + off];
        __syncthreads();
    }
    if (tid == 0) out[0] = s[0];
}

// ---------------- launch ----------------
extern "C" void kernel_launch(void* const* d_in, const int* in_sizes, int n_in,
                              void* d_out, int out_size) {
    const float* x       = (const float*)d_in[0];
    const float* tin     = (const float*)d_in[1];
    const float* maskp   = (const float*)d_in[2];
    const float* W_embed = (const float*)d_in[3];
    const float* b_embed = (const float*)d_in[4];
    const float* W_ih    = (const float*)d_in[5];
    const float* b_ih    = (const float*)d_in[6];
    const float* W_hh    = (const float*)d_in[7];
    const float* b_hh    = (const float*)d_in[8];
    const float* W_he    = (const float*)d_in[9];
    const float* b_he    = (const float*)d_in[10];
    const float* W_mu    = (const float*)d_in[11];
    const float* b_mu    = (const float*)d_in[12];
    const float* W_lv    = (const float*)d_in[13];
    const float* b_lv    = (const float*)d_in[14];
    const float* h_infl  = (const float*)d_in[15];
    const float* ti_p    = (const float*)d_in[16];
    const float* bi_p    = (const float*)d_in[17];
    float* out = (float*)d_out;

    k0_init<<<256, 256>>>();
    k1_embed<<<1024, 256>>>(x, W_embed, b_embed);
    k2_gates<<<dim3(512, 12), 256>>>(W_ih, b_ih);
    k3_gru<<<NGRU_BLK, 256>>>(W_hh, b_hh);
    k4a_he<<<dim3(512, 1), 256>>>(W_he, b_he);
    k4b_loss<<<NB4B, 256>>>(x, tin, maskp, W_mu, b_mu, W_lv, b_lv, h_infl, ti_p, bi_p);
    k5_reduce<<<1, 256>>>(out);
}

// round 3
// speedup vs baseline: 1.9303x; 1.9303x over previous
#include <cuda_runtime.h>

typedef unsigned long long ull;

#define TLEN 512
#define BSZ  128
#define MDIM 31
#define HSZ  512
#define ESZ  256
#define SSZ  128
#define G3   1536
#define TB   65536      // TLEN*BSZ
#define NSTEP 511
#define NGRU_BLK 128
#define HS_SLICE 65536  // BSZ*HSZ
#define NPAIR 65408     // 511*128
#define NB4B  8176      // NPAIR/8
#define LOG2PI 1.8378770664093453f

// ---------------- scratch (device globals; no allocation) ----------------
__device__ float g_phi[TB * ESZ];                    //  64 MB
__device__ float g_xg[(size_t)TB * G3];              // 402 MB
__device__ float g_hs[(size_t)TLEN * BSZ * HSZ];     // 134 MB  layout [t][i][k]
__device__ float g_hsT[(size_t)TLEN * BSZ * HSZ];    // 134 MB  layout [t][k][i]
__device__ float g_he[(size_t)TB * SSZ];             //  33 MB
__device__ float g_partial[NB4B];
__device__ unsigned g_arrive;

// ---------------- f32x2 packed-FMA helpers ----------------
__device__ __forceinline__ ull pk2(float x, float y) {
    ull r; asm("mov.b64 %0, {%1, %2};" : "=l"(r) : "f"(x), "f"(y)); return r;
}
__device__ __forceinline__ ull fma2(ull a, ull b, ull c) {
    ull d; asm("fma.rn.f32x2 %0, %1, %2, %3;" : "=l"(d) : "l"(a), "l"(b), "l"(c)); return d;
}
__device__ __forceinline__ float2 up2(ull v) {
    float2 f; asm("mov.b64 {%0, %1}, %2;" : "=f"(f.x), "=f"(f.y) : "l"(v)); return f;
}
__device__ __forceinline__ float sigm(float v) { return 1.f / (1.f + __expf(-v)); }

// ---------------- K0: init (zero h0 in both layouts, reset barrier) ----------------
__global__ void k0_init() {
    int idx = blockIdx.x * 256 + threadIdx.x;
    if (idx < HS_SLICE) { g_hs[idx] = 0.f; g_hsT[idx] = 0.f; }
    if (idx == 0) g_arrive = 0u;
}

// ---------------- K1: phi = relu(x @ W_embed^T + b_embed) ----------------
__global__ void __launch_bounds__(256) k1_embed(const float* __restrict__ x,
                                                const float* __restrict__ W_embed,
                                                const float* __restrict__ b_embed) {
    __shared__ float sx[64][32];
    const int tid = threadIdx.x;
    const int row0 = blockIdx.x * 64;
    for (int idx = tid; idx < 64 * MDIM; idx += 256) {
        int r = idx / MDIM, c = idx - r * MDIM;
        sx[r][c] = x[(size_t)(row0 + r) * MDIM + c];
    }
    float wreg[MDIM];
    const float* wp = W_embed + tid * MDIM;   // tid in [0,256) == ESZ
#pragma unroll
    for (int k = 0; k < MDIM; k++) wreg[k] = __ldg(wp + k);
    float bb = __ldg(b_embed + tid);
    __syncthreads();
#pragma unroll 4
    for (int r = 0; r < 64; r++) {
        float acc = bb;
#pragma unroll
        for (int k = 0; k < MDIM; k++) acc += sx[r][k] * wreg[k];
        g_phi[(size_t)(row0 + r) * ESZ + tid] = fmaxf(acc, 0.f);
    }
}

// ---------------- shared GEMM body: C[m,n] = act(sum_k A[m,k]*B[n,k] + bias[n]) ----------------
__device__ __forceinline__ void gemm_body(const float* __restrict__ A, const float* __restrict__ B,
                                          const float* __restrict__ bias, float* __restrict__ C,
                                          int KD, int N, bool relu) {
    __shared__ float As[16][128];
    __shared__ float Bs[16][128];
    const int tid = threadIdx.x;
    const int m0 = blockIdx.x * 128, n0 = blockIdx.y * 128;
    const int lr = tid >> 1, ls = (tid & 1) * 8;
    const int tx = tid & 15, ty = tid >> 4;
    ull acc[8][4];
#pragma unroll
    for (int i = 0; i < 8; i++)
#pragma unroll
        for (int j = 0; j < 4; j++) acc[i][j] = 0ull;

    const float* Ap = A + (size_t)(m0 + lr) * KD + ls;
    const float* Bp = B + (size_t)(n0 + lr) * KD + ls;

    for (int kt = 0; kt < KD; kt += 16) {
        float4 a0 = *(const float4*)(Ap + kt);
        float4 a1 = *(const float4*)(Ap + kt + 4);
        float4 b0 = *(const float4*)(Bp + kt);
        float4 b1 = *(const float4*)(Bp + kt + 4);
        __syncthreads();
        As[ls + 0][lr] = a0.x; As[ls + 1][lr] = a0.y; As[ls + 2][lr] = a0.z; As[ls + 3][lr] = a0.w;
        As[ls + 4][lr] = a1.x; As[ls + 5][lr] = a1.y; As[ls + 6][lr] = a1.z; As[ls + 7][lr] = a1.w;
        Bs[ls + 0][lr] = b0.x; Bs[ls + 1][lr] = b0.y; Bs[ls + 2][lr] = b0.z; Bs[ls + 3][lr] = b0.w;
        Bs[ls + 4][lr] = b1.x; Bs[ls + 5][lr] = b1.y; Bs[ls + 6][lr] = b1.z; Bs[ls + 7][lr] = b1.w;
        __syncthreads();
#pragma unroll
        for (int k = 0; k < 16; k++) {
            float4 av0 = *(const float4*)&As[k][ty * 8];
            float4 av1 = *(const float4*)&As[k][ty * 8 + 4];
            float4 bv0 = *(const float4*)&Bs[k][tx * 8];
            float4 bv1 = *(const float4*)&Bs[k][tx * 8 + 4];
            ull bp0 = pk2(bv0.x, bv0.y), bp1 = pk2(bv0.z, bv0.w);
            ull bp2 = pk2(bv1.x, bv1.y), bp3 = pk2(bv1.z, bv1.w);
            float aa[8] = {av0.x, av0.y, av0.z, av0.w, av1.x, av1.y, av1.z, av1.w};
#pragma unroll
            for (int i = 0; i < 8; i++) {
                ull ap = pk2(aa[i], aa[i]);
                acc[i][0] = fma2(ap, bp0, acc[i][0]);
                acc[i][1] = fma2(ap, bp1, acc[i][1]);
                acc[i][2] = fma2(ap, bp2, acc[i][2]);
                acc[i][3] = fma2(ap, bp3, acc[i][3]);
            }
        }
    }
    float bvals[8];
#pragma unroll
    for (int j = 0; j < 8; j++) bvals[j] = __ldg(bias + n0 + tx * 8 + j);
#pragma unroll
    for (int i = 0; i < 8; i++) {
        int row = m0 + ty * 8 + i;
        float out[8]; float2 v;
        v = up2(acc[i][0]); out[0] = v.x; out[1] = v.y;
        v = up2(acc[i][1]); out[2] = v.x; out[3] = v.y;
        v = up2(acc[i][2]); out[4] = v.x; out[5] = v.y;
        v = up2(acc[i][3]); out[6] = v.x; out[7] = v.y;
#pragma unroll
        for (int j = 0; j < 8; j++) {
            float o = out[j] + bvals[j];
            if (relu) o = fmaxf(o, 0.f);
            out[j] = o;
        }
        float4* dst = (float4*)(C + (size_t)row * N + n0 + tx * 8);
        dst[0] = make_float4(out[0], out[1], out[2], out[3]);
        dst[1] = make_float4(out[4], out[5], out[6], out[7]);
    }
}

__global__ void __launch_bounds__(256) k2_gates(const float* __restrict__ W_ih,
                                                const float* __restrict__ b_ih) {
    gemm_body(g_phi, W_ih, b_ih, g_xg, ESZ, G3, false);
}
__global__ void __launch_bounds__(256) k4a_he(const float* __restrict__ W_he,
                                              const float* __restrict__ b_he) {
    gemm_body(g_hs, W_he, b_he, g_he, HSZ, SSZ, true);
}

// ---------------- K3: persistent GRU, v2 ----------------
// 128 blocks x 1024 threads (one wave, 1 block/SM). Block owns 4 hidden units.
// Thread = (batch i = tid&127, unit-pair uu = (tid>>7)&1, K-quarter kq = tid>>8).
// h kept in transposed layout g_hsT[t][k][i] -> all h loads are fully coalesced LDG.32
// (1 line per warp-instruction instead of 32). Per-step K-partial reduction via smem.
__global__ void __launch_bounds__(1024, 1) k3_gru(const float* __restrict__ W_hh,
                                                  const float* __restrict__ b_hh) {
    __shared__ __align__(16) ull sW[3][2][512];   // 24 KB packed (w_j0,w_j1) pairs
    __shared__ ull sPart[1024][3];                // 24 KB per-thread partials
    const int tid = threadIdx.x;
    const int base = blockIdx.x * 4;

    for (int idx = tid; idx < 3 * 2 * 512; idx += 1024) {
        int k = idx & 511, uu_ = (idx >> 9) & 1, g = idx >> 10;
        int j0_ = base + uu_ * 2;
        float w0 = W_hh[(size_t)(g * HSZ + j0_) * HSZ + k];
        float w1 = W_hh[(size_t)(g * HSZ + j0_ + 1) * HSZ + k];
        sW[g][uu_][k] = pk2(w0, w1);
    }
    const int i  = tid & 127;
    const int uu = (tid >> 7) & 1;
    const int kq = tid >> 8;
    const int j0 = base + uu * 2;
    const float bhr0 = __ldg(b_hh + j0),            bhr1 = __ldg(b_hh + j0 + 1);
    const float bhz0 = __ldg(b_hh + HSZ + j0),      bhz1 = __ldg(b_hh + HSZ + j0 + 1);
    const float bhn0 = __ldg(b_hh + 2 * HSZ + j0),  bhn1 = __ldg(b_hh + 2 * HSZ + j0 + 1);
    __syncthreads();

    const ulonglong2* wr = (const ulonglong2*)&sW[0][uu][kq * 128];
    const ulonglong2* wz = (const ulonglong2*)&sW[1][uu][kq * 128];
    const ulonglong2* wn = (const ulonglong2*)&sW[2][uu][kq * 128];

    for (int t = 0; t < NSTEP; t++) {
        const float* hT  = g_hsT + (size_t)t * HS_SLICE;
        float*       hTn = g_hsT + (size_t)(t + 1) * HS_SLICE;
        float*       hSn = g_hs  + (size_t)(t + 1) * HS_SLICE;
        const float* xgr = g_xg + ((size_t)t * BSZ + i) * G3;

        // epilogue operands (only kq==0 threads use them) -- issue loads early
        float xr0 = 0.f, xr1 = 0.f, xz0 = 0.f, xz1 = 0.f, xn0 = 0.f, xn1 = 0.f;
        float hp0 = 0.f, hp1 = 0.f;
        if (kq == 0) {
            xr0 = __ldg(xgr + j0);           xr1 = __ldg(xgr + j0 + 1);
            xz0 = __ldg(xgr + HSZ + j0);     xz1 = __ldg(xgr + HSZ + j0 + 1);
            xn0 = __ldg(xgr + 2 * HSZ + j0); xn1 = __ldg(xgr + 2 * HSZ + j0 + 1);
            hp0 = __ldg(hT + (size_t)j0 * BSZ + i);
            hp1 = __ldg(hT + (size_t)(j0 + 1) * BSZ + i);
        }

        // coalesced h reads: element k of row i is hT[k*128 + i]
        const float* hk = hT + (size_t)kq * 128 * BSZ + i;

        ull accR = 0ull, accZ = 0ull, accN = 0ull;
#pragma unroll 8
        for (int kk = 0; kk < 64; kk++) {          // 2 K-values per iteration
            float h0 = __ldg(hk + (2 * kk) * BSZ);
            float h1 = __ldg(hk + (2 * kk + 1) * BSZ);
            ull hh0 = pk2(h0, h0), hh1 = pk2(h1, h1);
            ulonglong2 a = wr[kk];
            accR = fma2(hh0, a.x, accR); accR = fma2(hh1, a.y, accR);
            ulonglong2 b = wz[kk];
            accZ = fma2(hh0, b.x, accZ); accZ = fma2(hh1, b.y, accZ);
            ulonglong2 c = wn[kk];
            accN = fma2(hh0, c.x, accN); accN = fma2(hh1, c.y, accN);
        }
        sPart[tid][0] = accR; sPart[tid][1] = accZ; sPart[tid][2] = accN;
        __syncthreads();

        if (kq == 0) {
            float2 hr = up2(accR), hz = up2(accZ), hn = up2(accN);
#pragma unroll
            for (int q = 1; q < 4; q++) {
                float2 v;
                v = up2(sPart[tid + q * 256][0]); hr.x += v.x; hr.y += v.y;
                v = up2(sPart[tid + q * 256][1]); hz.x += v.x; hz.y += v.y;
                v = up2(sPart[tid + q * 256][2]); hn.x += v.x; hn.y += v.y;
            }
            float out0, out1;
            {
                float r = sigm(xr0 + hr.x + bhr0);
                float z = sigm(xz0 + hz.x + bhz0);
                float n = tanhf(xn0 + r * (hn.x + bhn0));
                out0 = (1.f - z) * n + z * hp0;
            }
            {
                float r = sigm(xr1 + hr.y + bhr1);
                float z = sigm(xz1 + hz.y + bhz1);
                float n = tanhf(xn1 + r * (hn.y + bhn1));
                out1 = (1.f - z) * n + z * hp1;
            }
            // transposed layout (for next step, coalesced)
            hTn[(size_t)j0 * BSZ + i]       = out0;
            hTn[(size_t)(j0 + 1) * BSZ + i] = out1;
            // standard layout (for k4a GEMM)
            hSn[(size_t)i * HSZ + j0]     = out0;
            hSn[(size_t)i * HSZ + j0 + 1] = out1;
        }
        // ---- grid barrier (monotonic counter) ----
        __threadfence();
        __syncthreads();
        if (tid == 0) {
            atomicAdd(&g_arrive, 1u);
            unsigned target = (unsigned)NGRU_BLK * (unsigned)(t + 1);
            while (*(volatile unsigned*)&g_arrive < target) { __nanosleep(32); }
            __threadfence();
        }
        __syncthreads();
    }
}

// ---------------- K4b: per-event loss (warp per (t,i)), partials per block ----------------
__global__ void __launch_bounds__(256) k4b_loss(const float* __restrict__ x,
                                                const float* __restrict__ tin,
                                                const float* __restrict__ maskp,
                                                const float* __restrict__ W_mu,
                                                const float* __restrict__ b_mu,
                                                const float* __restrict__ W_lv,
                                                const float* __restrict__ b_lv,
                                                const float* __restrict__ h_infl,
                                                const float* __restrict__ ti_p,
                                                const float* __restrict__ bi_p) {
    __shared__ float s_he[8][SSZ];
    __shared__ float s_red[8];
    const int tid = threadIdx.x;
    const int w = tid >> 5, lane = tid & 31;
    const int q = blockIdx.x * 8 + w;            // q in [0, 65408)
    const int t = (q >> 7) + 1;                  // t in [1, 512)
    const int i = q & 127;
    const size_t row = (size_t)t * BSZ + i;

    ((float4*)s_he[w])[lane] = ((const float4*)(g_he + row * SSZ))[lane];
    __syncwarp();

    float p = 0.f;
#pragma unroll
    for (int kk = 0; kk < 4; kk++) {
        int k = lane + 32 * kk;
        p += s_he[w][k] * __ldg(h_infl + k);
    }
#pragma unroll
    for (int off = 16; off; off >>= 1) p += __shfl_xor_sync(0xffffffffu, p, off);

    float marker = 0.f;
    if (lane < MDIM) {
        float accm = __ldg(b_mu + lane);
        float accl = __ldg(b_lv + lane);
        const float4* wm = (const float4*)(W_mu + lane * SSZ);
        const float4* wl = (const float4*)(W_lv + lane * SSZ);
#pragma unroll 8
        for (int kk = 0; kk < 32; kk++) {
            float4 hev = ((const float4*)s_he[w])[kk];
            float4 a = __ldg(wm + kk);
            float4 b = __ldg(wl + kk);
            accm += hev.x * a.x + hev.y * a.y + hev.z * a.z + hev.w * a.w;
            accl += hev.x * b.x + hev.y * b.y + hev.z * b.z + hev.w * b.w;
        }
        float xv = __ldg(x + row * MDIM + lane);
        float sig = fmaxf(expf(0.5f * accl), 0.01f);
        float d = (xv - accm) / sig;
        marker = -0.5f * d * d - logf(sig) - 0.5f * LOG2PI;
    }
#pragma unroll
    for (int off = 16; off; off >>= 1) marker += __shfl_xor_sync(0xffffffffu, marker, off);

    if (lane == 0) {
        float ti = __ldg(ti_p);
        float bi = __ldg(bi_p);
        float dt = __ldg(tin + row * 2 + 1);
        float term1 = p + ti * dt + bi;
        float time_ll = term1 + (expf(p + bi) - expf(term1)) / ti;
        float m = __ldg(maskp + row);
        s_red[w] = (-time_ll - marker) * m;    // GAMMA = 1
    }
    __syncthreads();
    if (tid == 0) {
        float s = 0.f;
#pragma unroll
        for (int k = 0; k < 8; k++) s += s_red[k];
        g_partial[blockIdx.x] = s;
    }
}

// ---------------- K5: deterministic final reduce ----------------
__global__ void __launch_bounds__(256) k5_reduce(float* __restrict__ out) {
    __shared__ float s[256];
    const int tid = threadIdx.x;
    float a = 0.f;
    for (int idx = tid; idx < NB4B; idx += 256) a += g_partial[idx];
    s[tid] = a;
    __syncthreads();
    for (int off = 128; off; off >>= 1) {
        if (tid < off) s[tid] += s[tid + off];
        __syncthreads();
    }
    if (tid == 0) out[0] = s[0];
}

// ---------------- launch ----------------
extern "C" void kernel_launch(void* const* d_in, const int* in_sizes, int n_in,
                              void* d_out, int out_size) {
    const float* x       = (const float*)d_in[0];
    const float* tin     = (const float*)d_in[1];
    const float* maskp   = (const float*)d_in[2];
    const float* W_embed = (const float*)d_in[3];
    const float* b_embed = (const float*)d_in[4];
    const float* W_ih    = (const float*)d_in[5];
    const float* b_ih    = (const float*)d_in[6];
    const float* W_hh    = (const float*)d_in[7];
    const float* b_hh    = (const float*)d_in[8];
    const float* W_he    = (const float*)d_in[9];
    const float* b_he    = (const float*)d_in[10];
    const float* W_mu    = (const float*)d_in[11];
    const float* b_mu    = (const float*)d_in[12];
    const float* W_lv    = (const float*)d_in[13];
    const float* b_lv    = (const float*)d_in[14];
    const float* h_infl  = (const float*)d_in[15];
    const float* ti_p    = (const float*)d_in[16];
    const float* bi_p    = (const float*)d_in[17];
    float* out = (float*)d_out;

    k0_init<<<512, 256>>>();
    k1_embed<<<1024, 256>>>(x, W_embed, b_embed);
    k2_gates<<<dim3(512, 12), 256>>>(W_ih, b_ih);
    k3_gru<<<NGRU_BLK, 1024>>>(W_hh, b_hh);
    k4a_he<<<dim3(512, 1), 256>>>(W_he, b_he);
    k4b_loss<<<NB4B, 256>>>(x, tin, maskp, W_mu, b_mu, W_lv, b_lv, h_infl, ti_p, bi_p);
    k5_reduce<<<1, 256>>>(out);
}